// round 13
// baseline (speedup 1.0000x reference)
#include <cuda_runtime.h>
#include <cuda_bf16.h>
#include <cstdint>

// out[flat] = x[flat] + pe[flat & 65535]
// pe[n,2k] = sin(n/(2000k/256+0.01)), pe[n,2k+1] = cos(same denom)
//
// R13: full bulk-async pipeline. Persistent blocks, 4-stage x 16KB smem
// ring. cp.async.bulk G2S (mbarrier complete_tx) -> add pe in smem ->
// cp.async.bulk S2G (bulk_group). DRAM sees 16KB sequential bursts both
// directions instead of warp-granular wavefronts.

#define N_POS 1024
#define ROW_VEC 64
#define PE_VEC (N_POS * ROW_VEC)       // 65536 float4
#define TOTAL_VEC (128 * PE_VEC)       // 8388608 float4
#define TILE_VEC 1024                  // float4 per tile (16KB)
#define TILE_BYTES (TILE_VEC * 16)
#define NT (TOTAL_VEC / TILE_VEC)      // 8192 tiles
#define STAGES 4
#define NTHREADS 256
#define GRID 304                       // 2 blocks/SM x 152 SMs

__device__ float4 g_pe[PE_VEC];

__global__ void pe_init_kernel() {
    int t = blockIdx.x * blockDim.x + threadIdx.x;   // (n,k) 0..131071
    int n = t >> 7, k = t & 127;
    const float denom = (2000.0f / 256.0f) * (float)k + 0.01f;
    float s, c;
    sincosf((float)n / denom, &s, &c);
    reinterpret_cast<float2*>(g_pe)[t] = make_float2(s, c);
}

__device__ __forceinline__ uint32_t smem_u32(const void* p) {
    uint32_t a;
    asm("{ .reg .u64 t; cvta.to.shared.u64 t, %1; cvt.u32.u64 %0, t; }"
        : "=r"(a) : "l"(p));
    return a;
}

__device__ __forceinline__ void mbar_wait(uint32_t mbar, uint32_t parity) {
    asm volatile(
        "{\n\t.reg .pred P;\n\t"
        "W_%=:\n\t"
        "mbarrier.try_wait.parity.shared::cta.b64 P, [%0], %1, 0x989680;\n\t"
        "@P bra.uni D_%=;\n\t"
        "bra.uni W_%=;\n\t"
        "D_%=:\n\t}"
        :: "r"(mbar), "r"(parity) : "memory");
}

__global__ void __launch_bounds__(NTHREADS) add_pe_tma(const float4* __restrict__ x,
                                                       float4* __restrict__ out) {
    extern __shared__ __align__(16) char smem[];            // STAGES*TILE_BYTES
    __shared__ __align__(8) uint64_t mbar_s[STAGES];

    const int tid = threadIdx.x;
    const int bid = blockIdx.x;
    float4* bufs = reinterpret_cast<float4*>(smem);
    const uint32_t mbar0 = smem_u32(&mbar_s[0]);
    const uint32_t sbase = smem_u32(smem);

    if (tid < STAGES) {
        asm volatile("mbarrier.init.shared.b64 [%0], 1;"
                     :: "r"(mbar0 + tid * 8) : "memory");
    }
    __syncthreads();
    if (tid == 0)
        asm volatile("fence.proxy.async.shared::cta;" ::: "memory");
    __syncthreads();

    const int nloc = (NT - bid + GRID - 1) / GRID;          // tiles this block

    // Prologue: issue loads for local tiles 0..STAGES-2
    if (tid == 0) {
#pragma unroll
        for (int j = 0; j < STAGES - 1; ++j) {
            if (j < nloc) {
                const int t = bid + j * GRID;
                const uint32_t mb = mbar0 + (j & (STAGES - 1)) * 8;
                const uint32_t dst = sbase + (j & (STAGES - 1)) * TILE_BYTES;
                asm volatile("mbarrier.arrive.expect_tx.shared.b64 _, [%0], %1;"
                             :: "r"(mb), "r"((uint32_t)TILE_BYTES) : "memory");
                asm volatile(
                    "cp.async.bulk.shared::cta.global.mbarrier::complete_tx::bytes "
                    "[%0], [%1], %2, [%3];"
                    :: "r"(dst), "l"(x + (size_t)t * TILE_VEC),
                       "r"((uint32_t)TILE_BYTES), "r"(mb) : "memory");
            }
        }
    }

    for (int j = 0; j < nloc; ++j) {
        const int slot = j & (STAGES - 1);
        const int t = bid + j * GRID;
        const uint32_t gbase = (uint32_t)t * TILE_VEC;

        // Wait for this tile's load
        mbar_wait(mbar0 + slot * 8, (j >> 2) & 1);

        // Add pe in smem (4 float4 per thread)
        float4* buf = bufs + slot * TILE_VEC;
#pragma unroll
        for (int v = 0; v < TILE_VEC / NTHREADS; ++v) {
            const int idx = tid + v * NTHREADS;
            const float4 p = __ldg(&g_pe[(gbase + idx) & (PE_VEC - 1)]);
            float4 a = buf[idx];
            a.x += p.x; a.y += p.y; a.z += p.z; a.w += p.w;
            buf[idx] = a;
        }
        __syncthreads();

        if (tid == 0) {
            // Bulk store this tile
            asm volatile("fence.proxy.async.shared::cta;" ::: "memory");
            asm volatile(
                "cp.async.bulk.global.shared::cta.bulk_group [%0], [%1], %2;"
                :: "l"(out + (size_t)t * TILE_VEC),
                   "r"(sbase + slot * TILE_BYTES),
                   "r"((uint32_t)TILE_BYTES) : "memory");
            asm volatile("cp.async.bulk.commit_group;" ::: "memory");

            // Issue load for tile j+STAGES-1 (reuses slot of tile j-1;
            // wait until only the just-committed store is outstanding)
            const int jn = j + STAGES - 1;
            if (jn < nloc) {
                asm volatile("cp.async.bulk.wait_group.read 1;" ::: "memory");
                const int tn = bid + jn * GRID;
                const int sn = jn & (STAGES - 1);
                const uint32_t mb = mbar0 + sn * 8;
                asm volatile("mbarrier.arrive.expect_tx.shared.b64 _, [%0], %1;"
                             :: "r"(mb), "r"((uint32_t)TILE_BYTES) : "memory");
                asm volatile(
                    "cp.async.bulk.shared::cta.global.mbarrier::complete_tx::bytes "
                    "[%0], [%1], %2, [%3];"
                    :: "r"(sbase + sn * TILE_BYTES),
                       "l"(x + (size_t)tn * TILE_VEC),
                       "r"((uint32_t)TILE_BYTES), "r"(mb) : "memory");
            }
        }
        // No extra sync needed: next iteration's mbar_wait gates consumers.
    }

    // Drain outstanding stores before exit
    if (tid == 0)
        asm volatile("cp.async.bulk.wait_group 0;" ::: "memory");
}

extern "C" void kernel_launch(void* const* d_in, const int* in_sizes, int n_in,
                              void* d_out, int out_size) {
    const float4* x = (const float4*)d_in[0];
    float4* out = (float4*)d_out;

    cudaFuncSetAttribute(add_pe_tma,
                         cudaFuncAttributeMaxDynamicSharedMemorySize,
                         STAGES * TILE_BYTES);
    pe_init_kernel<<<512, 256>>>();
    add_pe_tma<<<GRID, NTHREADS, STAGES * TILE_BYTES>>>(x, out);
}

// round 16
// speedup vs baseline: 1.0158x; 1.0158x over previous
#include <cuda_runtime.h>
#include <cuda_bf16.h>
#include <cstdint>

// out[b,s,n,c] = x[b,s,n,c] + pe[n,c],  x: (8,16,1024,256) fp32
// pe[n,2k]   = sin(n / (2000*k/256 + 0.01))
// pe[n,2k+1] = cos(n / (2000*k/256 + 0.01))
//
// R15: R4's fused kernel + asymmetric L2 eviction via createpolicy +
// ld/st.global.L2::cache_hint (the form ptxas accepts for .v4.f32).
//   x loads : evict_first policy (stream, don't retain)
//   out sts : evict_last policy (retain dirty lines across graph replays;
//             out=128MB ~ L2=126MB -> repeat stores become L2 write hits)

#define N_POS 1024
#define D_DIM 256
#define ROW_VEC (D_DIM / 4)     // 64 float4 per row
#define REPS 128                // B*S
#define REPS_PER_BLK 64         // gridDim.y = 2
#define BATCH 8

__device__ __forceinline__ uint64_t policy_evict_first() {
    uint64_t pol;
    asm("createpolicy.fractional.L2::evict_first.b64 %0, 1.0;" : "=l"(pol));
    return pol;
}

__device__ __forceinline__ uint64_t policy_evict_last() {
    uint64_t pol;
    asm("createpolicy.fractional.L2::evict_last.b64 %0, 1.0;" : "=l"(pol));
    return pol;
}

__device__ __forceinline__ float4 ldg_hint(const float4* p, uint64_t pol) {
    float4 v;
    asm volatile("ld.global.nc.L2::cache_hint.v4.f32 {%0,%1,%2,%3}, [%4], %5;"
                 : "=f"(v.x), "=f"(v.y), "=f"(v.z), "=f"(v.w)
                 : "l"(p), "l"(pol));
    return v;
}

__device__ __forceinline__ void stg_hint(float4* p, float4 v, uint64_t pol) {
    asm volatile("st.global.L2::cache_hint.v4.f32 [%0], {%1,%2,%3,%4}, %5;"
                 :: "l"(p), "f"(v.x), "f"(v.y), "f"(v.z), "f"(v.w), "l"(pol)
                 : "memory");
}

__global__ void __launch_bounds__(256) add_pe_fused(const float4* __restrict__ x,
                                                    float4* __restrict__ out) {
    __shared__ float4 s_pe[ROW_VEC];

    const int n = blockIdx.x;           // position 0..1023
    const int t = threadIdx.x;

    if (t < 128) {
        const float denom = (2000.0f / 256.0f) * (float)t + 0.01f;
        float s, c;
        sincosf((float)n / denom, &s, &c);
        reinterpret_cast<float2*>(s_pe)[t] = make_float2(s, c);
    }
    __syncthreads();

    const uint64_t pol_first = policy_evict_first();
    const uint64_t pol_last  = policy_evict_last();

    const int lane = t & (ROW_VEC - 1);   // 0..63 float4 within row
    const int rsub = t >> 6;              // 0..3
    const float4 p = s_pe[lane];

    const unsigned rstride = N_POS * ROW_VEC;             // 65536 float4 / rep
    const int r0 = blockIdx.y * REPS_PER_BLK + rsub;
    const unsigned base = (unsigned)(r0 * N_POS + n) * ROW_VEC + lane;
    const unsigned bstride = 4u * rstride;                // between batched reps
    const unsigned ostride = (unsigned)BATCH * bstride;   // between outer iters

#pragma unroll
    for (int it = 0; it < REPS_PER_BLK / (4 * BATCH); ++it) {   // 2 iters
        const unsigned b = base + (unsigned)it * ostride;
        float4 a[BATCH];
#pragma unroll
        for (int j = 0; j < BATCH; ++j)
            a[j] = ldg_hint(&x[b + (unsigned)j * bstride], pol_first);
#pragma unroll
        for (int j = 0; j < BATCH; ++j) {
            a[j].x += p.x; a[j].y += p.y; a[j].z += p.z; a[j].w += p.w;
        }
#pragma unroll
        for (int j = 0; j < BATCH; ++j)
            stg_hint(&out[b + (unsigned)j * bstride], a[j], pol_last);
    }
}

extern "C" void kernel_launch(void* const* d_in, const int* in_sizes, int n_in,
                              void* d_out, int out_size) {
    const float4* x = (const float4*)d_in[0];
    float4* out = (float4*)d_out;
    dim3 grid(N_POS, REPS / REPS_PER_BLK, 1);   // (1024, 2)
    add_pe_fused<<<grid, 256>>>(x, out);
}

// round 17
// speedup vs baseline: 1.0415x; 1.0253x over previous
#include <cuda_runtime.h>
#include <cuda_bf16.h>
#include <cstdint>

// out[b,s,n,c] = x[b,s,n,c] + pe[n,c],  x: (8,16,1024,256) fp32
// pe[n,2k]   = sin(n / (2000*k/256 + 0.01))
// pe[n,2k+1] = cos(n / (2000*k/256 + 0.01))
//
// R17: R4's fused MLP-batched kernel with 256-bit (v8.b32) global accesses.
// Each thread moves 4 x 32B per iteration (same bytes as R4's 8 x 16B) but
// in half the instructions / LSU wavefronts, presenting wider DRAM bursts.

#define N_POS 1024
#define D_DIM 256
#define ROW_VEC (D_DIM / 4)     // 64 float4 per row
#define ROW_V8 (D_DIM / 8)      // 32 float8 per row
#define REPS 128                // B*S
#define REPS_PER_BLK 64         // gridDim.y = 2
#define BATCH 4                 // 4 x 32B in flight per thread

struct F8 { float v[8]; };

__device__ __forceinline__ F8 ldg256(const float* p) {
    F8 r;
    uint32_t u0,u1,u2,u3,u4,u5,u6,u7;
    asm volatile("ld.global.nc.L2::evict_first.v8.b32 "
                 "{%0,%1,%2,%3,%4,%5,%6,%7}, [%8];"
                 : "=r"(u0),"=r"(u1),"=r"(u2),"=r"(u3),
                   "=r"(u4),"=r"(u5),"=r"(u6),"=r"(u7)
                 : "l"(p));
    r.v[0]=__uint_as_float(u0); r.v[1]=__uint_as_float(u1);
    r.v[2]=__uint_as_float(u2); r.v[3]=__uint_as_float(u3);
    r.v[4]=__uint_as_float(u4); r.v[5]=__uint_as_float(u5);
    r.v[6]=__uint_as_float(u6); r.v[7]=__uint_as_float(u7);
    return r;
}

__device__ __forceinline__ void stg256(float* p, const F8& r) {
    asm volatile("st.global.L2::evict_first.v8.b32 [%0], "
                 "{%1,%2,%3,%4,%5,%6,%7,%8};"
                 :: "l"(p),
                    "r"(__float_as_uint(r.v[0])), "r"(__float_as_uint(r.v[1])),
                    "r"(__float_as_uint(r.v[2])), "r"(__float_as_uint(r.v[3])),
                    "r"(__float_as_uint(r.v[4])), "r"(__float_as_uint(r.v[5])),
                    "r"(__float_as_uint(r.v[6])), "r"(__float_as_uint(r.v[7]))
                 : "memory");
}

__global__ void __launch_bounds__(256) add_pe_fused(const float* __restrict__ x,
                                                    float* __restrict__ out) {
    __shared__ __align__(32) float s_pe[D_DIM];

    const int n = blockIdx.x;           // position 0..1023
    const int t = threadIdx.x;

    if (t < 128) {
        const float denom = (2000.0f / 256.0f) * (float)t + 0.01f;
        float s, c;
        sincosf((float)n / denom, &s, &c);
        reinterpret_cast<float2*>(s_pe)[t] = make_float2(s, c);
    }
    __syncthreads();

    const int lane8 = t & (ROW_V8 - 1);   // 0..31 float8 within row
    const int rsub  = t >> 5;             // 0..7

    F8 p;
#pragma unroll
    for (int e = 0; e < 8; ++e) p.v[e] = s_pe[lane8 * 8 + e];

    // Thread handles reps r0+rsub+8*m, m=0..7, in 2 batches of 4.
    const unsigned repstride = N_POS * ROW_V8;           // float8 per rep (32768)
    const int r0 = blockIdx.y * REPS_PER_BLK + rsub;
    const unsigned base = (unsigned)(r0 * N_POS + n) * ROW_V8 + lane8;
    const unsigned mstride = 8u * repstride;             // per m-step

#pragma unroll
    for (int it = 0; it < 2; ++it) {
        F8 a[BATCH];
#pragma unroll
        for (int j = 0; j < BATCH; ++j)
            a[j] = ldg256(x + (size_t)(base + (unsigned)(it * BATCH + j) * mstride) * 8u);
#pragma unroll
        for (int j = 0; j < BATCH; ++j)
#pragma unroll
            for (int e = 0; e < 8; ++e)
                a[j].v[e] += p.v[e];
#pragma unroll
        for (int j = 0; j < BATCH; ++j)
            stg256(out + (size_t)(base + (unsigned)(it * BATCH + j) * mstride) * 8u, a[j]);
    }
}

extern "C" void kernel_launch(void* const* d_in, const int* in_sizes, int n_in,
                              void* d_out, int out_size) {
    const float* x = (const float*)d_in[0];
    float* out = (float*)d_out;
    dim3 grid(N_POS, REPS / REPS_PER_BLK, 1);   // (1024, 2)
    add_pe_fused<<<grid, 256>>>(x, out);
}